// round 1
// baseline (speedup 1.0000x reference)
#include <cuda_runtime.h>
#include <cuda_bf16.h>
#include <math.h>

// ---------------- problem constants ----------------
#define BB 32
#define NN 385
#define DIM 512
#define HH 8
#define HD 64
#define TDIM 1536
#define MLP 2048
#define KA 45
#define KM 135
#define KS 90
#define RN 271            // 1 + 45 + 135 + 90
#define M1 (BB*NN)        // 12320
#define M2 (BB*RN)        // 8672

// d_out layout (tuple flattened, all float32)
#define X_SZ   ((long long)BB*RN*DIM)          // 4,440,064
#define OFF_IA (X_SZ)
#define OFF_IM (OFF_IA + (long long)BB*KA)     // +1440
#define OFF_IS (OFF_IM + (long long)BB*KM)     // +4320
#define OFF_MASK (OFF_IS + (long long)BB*KS)   // +2880
#define MASK_SZ ((long long)BB*RN*RN)          // 2,350,112

// ---------------- scratch (static device allocations) ----------------
__device__ float g_xn  [M1*DIM];
__device__ float g_qkv [(size_t)M1*TDIM];
__device__ float g_xatt[M1*DIM];
__device__ float g_xres[M1*DIM];
__device__ float g_clsP[BB*HH*384];
__device__ float g_cls [BB*384];
__device__ int   g_idx [BB*(KA+KM+KS)];
__device__ float g_xg  [M2*DIM];
__device__ float g_xn2 [M2*DIM];
__device__ float g_h   [(size_t)M2*MLP];

// ---------------- LayerNorm (row length 512, 256 threads) ----------------
__global__ void ln_kernel(const float* __restrict__ in, const float* __restrict__ g,
                          const float* __restrict__ bta, float* __restrict__ out) {
    int r = blockIdx.x;
    int t = threadIdx.x;
    const float* xr = in + (size_t)r * DIM;
    float a = xr[t], c = xr[t + 256];
    __shared__ float rs[256], rq[256];
    rs[t] = a + c; rq[t] = a*a + c*c;
    __syncthreads();
    for (int st = 128; st > 0; st >>= 1) {
        if (t < st) { rs[t] += rs[t+st]; rq[t] += rq[t+st]; }
        __syncthreads();
    }
    float mu  = rs[0] * (1.0f/512.0f);
    float var = rq[0] * (1.0f/512.0f) - mu*mu;
    float inv = rsqrtf(var + 1e-5f);
    out[(size_t)r*DIM + t]       = (a - mu) * inv * g[t]     + bta[t];
    out[(size_t)r*DIM + t + 256] = (c - mu) * inv * g[t+256] + bta[t+256];
}

// ---------------- SGEMM: C[M,Nc] = A[M,K] @ Bw[Nc,K]^T (+epilogue) ----------------
// EPI: 0 = none, 1 = +bias +residual, 2 = +bias +exact GELU
template<int EPI>
__global__ void gemm_tn(const float* __restrict__ A, const float* __restrict__ Bw,
                        const float* __restrict__ bias, const float* __restrict__ res,
                        float* __restrict__ C, int M, int Nc, int K) {
    const int BM = 128, BN = 128, BK = 8;
    __shared__ float As[BK][BM];
    __shared__ float Bs[BK][BN];
    int bm = blockIdx.y * BM;
    int bn = blockIdx.x * BN;
    int tid = threadIdx.x;
    int tx = tid & 15, ty = tid >> 4;
    int lr = tid >> 1;            // 0..127
    int lc = (tid & 1) * 4;       // 0 or 4

    float acc[8][8];
#pragma unroll
    for (int i = 0; i < 8; i++)
#pragma unroll
        for (int j = 0; j < 8; j++) acc[i][j] = 0.f;

    for (int k0 = 0; k0 < K; k0 += BK) {
        int gr = bm + lr;
        float4 a4 = make_float4(0.f,0.f,0.f,0.f);
        if (gr < M) a4 = *reinterpret_cast<const float4*>(&A[(size_t)gr*K + k0 + lc]);
        As[lc+0][lr] = a4.x; As[lc+1][lr] = a4.y; As[lc+2][lr] = a4.z; As[lc+3][lr] = a4.w;
        int gn = bn + lr;
        float4 b4 = make_float4(0.f,0.f,0.f,0.f);
        if (gn < Nc) b4 = *reinterpret_cast<const float4*>(&Bw[(size_t)gn*K + k0 + lc]);
        Bs[lc+0][lr] = b4.x; Bs[lc+1][lr] = b4.y; Bs[lc+2][lr] = b4.z; Bs[lc+3][lr] = b4.w;
        __syncthreads();
#pragma unroll
        for (int k = 0; k < BK; k++) {
            float4 a0 = *reinterpret_cast<const float4*>(&As[k][ty*8]);
            float4 a1 = *reinterpret_cast<const float4*>(&As[k][ty*8+4]);
            float4 b0 = *reinterpret_cast<const float4*>(&Bs[k][tx*8]);
            float4 b1 = *reinterpret_cast<const float4*>(&Bs[k][tx*8+4]);
            float av[8] = {a0.x,a0.y,a0.z,a0.w,a1.x,a1.y,a1.z,a1.w};
            float bv[8] = {b0.x,b0.y,b0.z,b0.w,b1.x,b1.y,b1.z,b1.w};
#pragma unroll
            for (int i = 0; i < 8; i++)
#pragma unroll
                for (int j = 0; j < 8; j++) acc[i][j] += av[i]*bv[j];
        }
        __syncthreads();
    }

#pragma unroll
    for (int i = 0; i < 8; i++) {
        int row = bm + ty*8 + i;
        if (row >= M) continue;
#pragma unroll
        for (int j = 0; j < 8; j++) {
            int col = bn + tx*8 + j;
            float v = acc[i][j];
            if (EPI == 1) v += bias[col] + res[(size_t)row*Nc + col];
            if (EPI == 2) {
                v += bias[col];
                v = 0.5f * v * (1.0f + erff(v * 0.70710678118654752f));
            }
            C[(size_t)row*Nc + col] = v;
        }
    }
}

// ---------------- fused attention per (b,h): K/V resident in smem ----------------
__global__ void attn_kernel(const float* __restrict__ mask) {
    extern __shared__ float dyn[];
    float* Ks = dyn;                 // 385*65
    float* Vs = dyn + 385*65;        // 385*65
    __shared__ float q_s[64];
    __shared__ float sc[385];
    __shared__ float red[256];
    __shared__ float accs[256];

    int bh = blockIdx.x;
    int b = bh >> 3, h = bh & 7;
    int t = threadIdx.x;
    const float* qkvb = g_qkv + (size_t)b * NN * TDIM;

    for (int i = t; i < NN*HD; i += 256) {
        int m = i >> 6, d = i & 63;
        Ks[m*65 + d] = qkvb[(size_t)m*TDIM + DIM     + h*HD + d];
        Vs[m*65 + d] = qkvb[(size_t)m*TDIM + 2*DIM   + h*HD + d];
    }
    __syncthreads();

    const float scale = 0.125f;                 // hd^-0.5 = 1/8
    const float addc  = 1e-6f / (float)NN;
    int d = t & 63, q4 = t >> 6;

    for (int n = 0; n < NN; n++) {
        if (t < 64) q_s[t] = qkvb[(size_t)n*TDIM + h*HD + t];
        __syncthreads();

        float lmax = -INFINITY;
        for (int m = t; m < NN; m += 256) {
            float dot = 0.f;
#pragma unroll
            for (int dd = 0; dd < 64; dd++) dot += q_s[dd] * Ks[m*65 + dd];
            dot *= scale;
            sc[m] = dot;
            lmax = fmaxf(lmax, dot);
        }
        red[t] = lmax; __syncthreads();
        for (int s = 128; s > 0; s >>= 1) {
            if (t < s) red[t] = fmaxf(red[t], red[t+s]);
            __syncthreads();
        }
        float mx = red[0];
        __syncthreads();

        float lsum = 0.f;
        const float* mrow = mask + ((size_t)b*NN + n) * NN;
        for (int m = t; m < NN; m += 256) {
            float e = expf(sc[m] - mx) * mrow[m];
            sc[m] = e;
            lsum += e;
        }
        red[t] = lsum; __syncthreads();
        for (int s = 128; s > 0; s >>= 1) {
            if (t < s) red[t] += red[t+s];
            __syncthreads();
        }
        float inv = 1.0f / (red[0] + 1e-6f);
        __syncthreads();

        for (int m = t; m < NN; m += 256) sc[m] = (sc[m] + addc) * inv;
        __syncthreads();

        if (n == 0) {
            for (int j = t; j < 384; j += 256)
                g_clsP[((size_t)b*HH + h)*384 + j] = sc[1 + j] * 0.125f;
        }

        float partial = 0.f;
        for (int m = q4; m < NN; m += 4) partial += sc[m] * Vs[m*65 + d];
        accs[t] = partial; __syncthreads();
        if (t < 64) {
            float o = accs[d] + accs[64+d] + accs[128+d] + accs[192+d];
            g_xatt[((size_t)(b*NN + n))*DIM + h*HD + d] = o;
        }
        __syncthreads();
    }
}

// ---------------- cls head reduce ----------------
__global__ void cls_reduce_kernel() {
    int i = blockIdx.x*256 + threadIdx.x;
    if (i < BB*384) {
        int b = i / 384, j = i % 384;
        float s = 0.f;
#pragma unroll
        for (int h = 0; h < HH; h++) s += g_clsP[((size_t)b*HH + h)*384 + j];
        g_cls[i] = s;
    }
}

// ---------------- per-(b,group) exact top-k (jax tie semantics) ----------------
__global__ void topk_kernel(float* __restrict__ out) {
    const int nsz_[3]  = {64, 192, 128};
    const int kk_[3]   = {KA, KM, KS};
    const int base_[3] = {0, 64, 256};
    const int ib_[3]   = {0, KA, KA+KM};
    const long long ob_[3] = {OFF_IA, OFF_IM, OFF_IS};
    const int os_[3]   = {KA, KM, KS};

    int b = blockIdx.x / 3, g = blockIdx.x % 3;
    int nsz = nsz_[g], kk = kk_[g];
    __shared__ float v[192];
    __shared__ float rv[256];
    __shared__ int   ri[256];
    int t = threadIdx.x;
    if (t < nsz) v[t] = g_cls[b*384 + base_[g] + t];
    __syncthreads();

    for (int i = 0; i < kk; i++) {
        rv[t] = (t < nsz) ? v[t] : -INFINITY;
        ri[t] = t;
        __syncthreads();
        for (int s = 128; s > 0; s >>= 1) {
            if (t < s) {
                float v2 = rv[t+s]; int i2 = ri[t+s];
                if (v2 > rv[t] || (v2 == rv[t] && i2 < ri[t])) { rv[t] = v2; ri[t] = i2; }
            }
            __syncthreads();
        }
        if (t == 0) {
            int w = ri[0];
            g_idx[b*(KA+KM+KS) + ib_[g] + i] = w;
            out[ob_[g] + (long long)b*os_[g] + i] = (float)w;
            v[w] = -INFINITY;
        }
        __syncthreads();
    }
}

// ---------------- gather pruned rows ----------------
__global__ void gather_kernel() {
    int r = blockIdx.x;
    int b = r / RN, p = r % RN;
    int s;
    if (p == 0)            s = 0;
    else if (p < 1+KA)     s = 1   + g_idx[b*(KA+KM+KS) + (p-1)];
    else if (p < 1+KA+KM)  s = 65  + g_idx[b*(KA+KM+KS) + KA + (p-1-KA)];
    else                   s = 257 + g_idx[b*(KA+KM+KS) + KA+KM + (p-1-KA-KM)];
    const float4* src = reinterpret_cast<const float4*>(g_xres + ((size_t)(b*NN + s))*DIM);
    float4* dst = reinterpret_cast<float4*>(g_xg + (size_t)r*DIM);
    dst[threadIdx.x] = src[threadIdx.x];
}

// ---------------- new_mask is provably all-ones ----------------
__global__ void mask_fill_kernel(float* __restrict__ out) {
    long long i = (long long)blockIdx.x*256 + threadIdx.x;
    if (i < MASK_SZ) out[OFF_MASK + i] = 1.0f;
}

// ---------------- launcher ----------------
extern "C" void kernel_launch(void* const* d_in, const int* in_sizes, int n_in,
                              void* d_out, int out_size) {
    const float* x     = (const float*)d_in[0];
    const float* amask = (const float*)d_in[1];
    const float* Wqkv  = (const float*)d_in[5];
    const float* Wproj = (const float*)d_in[6];
    const float* bproj = (const float*)d_in[7];
    const float* g1    = (const float*)d_in[8];
    const float* b1    = (const float*)d_in[9];
    const float* g2    = (const float*)d_in[10];
    const float* b2    = (const float*)d_in[11];
    const float* Wfc1  = (const float*)d_in[12];
    const float* bfc1  = (const float*)d_in[13];
    const float* Wfc2  = (const float*)d_in[14];
    const float* bfc2  = (const float*)d_in[15];
    float* out = (float*)d_out;

    // resolve scratch device pointers
    float *p_xn, *p_qkv, *p_xatt, *p_xres, *p_xg, *p_xn2, *p_h;
    cudaGetSymbolAddress((void**)&p_xn,   g_xn);
    cudaGetSymbolAddress((void**)&p_qkv,  g_qkv);
    cudaGetSymbolAddress((void**)&p_xatt, g_xatt);
    cudaGetSymbolAddress((void**)&p_xres, g_xres);
    cudaGetSymbolAddress((void**)&p_xg,   g_xg);
    cudaGetSymbolAddress((void**)&p_xn2,  g_xn2);
    cudaGetSymbolAddress((void**)&p_h,    g_h);

    const int ATTN_SMEM = 2 * 385 * 65 * (int)sizeof(float);  // 200,200 B
    cudaFuncSetAttribute(attn_kernel, cudaFuncAttributeMaxDynamicSharedMemorySize, ATTN_SMEM);

    // 1) LN1
    ln_kernel<<<M1, 256>>>(x, g1, b1, p_xn);
    // 2) QKV GEMM
    gemm_tn<0><<<dim3(TDIM/128, (M1+127)/128), 256>>>(p_xn, Wqkv, nullptr, nullptr, p_qkv, M1, TDIM, DIM);
    // 3) attention (fused softmax + AV + cls row)
    attn_kernel<<<BB*HH, 256, ATTN_SMEM>>>(amask);
    // 4) proj + bias + residual
    gemm_tn<1><<<dim3(DIM/128, (M1+127)/128), 256>>>(p_xatt, Wproj, bproj, x, p_xres, M1, DIM, DIM);
    // 5) cls reduce + top-k (writes idx floats into d_out)
    cls_reduce_kernel<<<(BB*384 + 255)/256, 256>>>();
    topk_kernel<<<BB*3, 256>>>(out);
    // 6) gather pruned tokens
    gather_kernel<<<M2, 128>>>();
    // 7) new_mask = ones
    mask_fill_kernel<<<(int)((MASK_SZ + 255)/256), 256>>>(out);
    // 8) LN2
    ln_kernel<<<M2, 256>>>(p_xg, g2, b2, p_xn2);
    // 9) fc1 + bias + exact GELU
    gemm_tn<2><<<dim3(MLP/128, (M2+127)/128), 256>>>(p_xn2, Wfc1, bfc1, nullptr, p_h, M2, MLP, DIM);
    // 10) fc2 + bias + residual -> final x into d_out
    gemm_tn<1><<<dim3(DIM/128, (M2+127)/128), 256>>>(p_h, Wfc2, bfc2, p_xg, out, M2, DIM, MLP);
}

// round 2
// speedup vs baseline: 1.0012x; 1.0012x over previous
#include <cuda_runtime.h>
#include <cuda_bf16.h>
#include <math.h>

// ---------------- problem constants ----------------
#define BB 32
#define NN 385
#define DIM 512
#define HH 8
#define HD 64
#define TDIM 1536
#define MLP 2048
#define KA 45
#define KM 135
#define KS 90
#define RN 271            // 1 + 45 + 135 + 90
#define M1 (BB*NN)        // 12320
#define M2 (BB*RN)        // 8672

// d_out layout (tuple flattened, all float32)
#define X_SZ   ((long long)BB*RN*DIM)          // 4,440,064
#define OFF_IA (X_SZ)
#define OFF_IM (OFF_IA + (long long)BB*KA)     // +1440
#define OFF_IS (OFF_IM + (long long)BB*KM)     // +4320
#define OFF_MASK (OFF_IS + (long long)BB*KS)   // +2880
#define MASK_SZ ((long long)BB*RN*RN)          // 2,350,112

// ---------------- scratch (static device allocations) ----------------
__device__ float g_xn  [M1*DIM];
__device__ float g_qkv [(size_t)M1*TDIM];
__device__ float g_xatt[M1*DIM];
__device__ float g_xres[M1*DIM];
__device__ float g_clsP[BB*HH*384];
__device__ float g_cls [BB*384];
__device__ int   g_idx [BB*(KA+KM+KS)];
__device__ float g_xg  [M2*DIM];
__device__ float g_xn2 [M2*DIM];
__device__ float g_h   [(size_t)M2*MLP];

// ---------------- LayerNorm (row length 512, 256 threads) ----------------
__global__ void ln_kernel(const float* __restrict__ in, const float* __restrict__ g,
                          const float* __restrict__ bta, float* __restrict__ out) {
    int r = blockIdx.x;
    int t = threadIdx.x;
    const float* xr = in + (size_t)r * DIM;
    float a = xr[t], c = xr[t + 256];
    __shared__ float rs[256], rq[256];
    rs[t] = a + c; rq[t] = a*a + c*c;
    __syncthreads();
    for (int st = 128; st > 0; st >>= 1) {
        if (t < st) { rs[t] += rs[t+st]; rq[t] += rq[t+st]; }
        __syncthreads();
    }
    float mu  = rs[0] * (1.0f/512.0f);
    float var = rq[0] * (1.0f/512.0f) - mu*mu;
    float inv = rsqrtf(var + 1e-5f);
    out[(size_t)r*DIM + t]       = (a - mu) * inv * g[t]     + bta[t];
    out[(size_t)r*DIM + t + 256] = (c - mu) * inv * g[t+256] + bta[t+256];
}

// ---------------- SGEMM: C[M,Nc] = A[M,K] @ Bw[Nc,K]^T (+epilogue) ----------------
// EPI: 0 = none, 1 = +bias +residual, 2 = +bias +exact GELU
template<int EPI>
__global__ void gemm_tn(const float* __restrict__ A, const float* __restrict__ Bw,
                        const float* __restrict__ bias, const float* __restrict__ res,
                        float* __restrict__ C, int M, int Nc, int K) {
    const int BM = 128, BN = 128, BK = 8;
    __shared__ float As[BK][BM];
    __shared__ float Bs[BK][BN];
    int bm = blockIdx.y * BM;
    int bn = blockIdx.x * BN;
    int tid = threadIdx.x;
    int tx = tid & 15, ty = tid >> 4;
    int lr = tid >> 1;            // 0..127
    int lc = (tid & 1) * 4;       // 0 or 4

    float acc[8][8];
#pragma unroll
    for (int i = 0; i < 8; i++)
#pragma unroll
        for (int j = 0; j < 8; j++) acc[i][j] = 0.f;

    for (int k0 = 0; k0 < K; k0 += BK) {
        int gr = bm + lr;
        float4 a4 = make_float4(0.f,0.f,0.f,0.f);
        if (gr < M) a4 = *reinterpret_cast<const float4*>(&A[(size_t)gr*K + k0 + lc]);
        As[lc+0][lr] = a4.x; As[lc+1][lr] = a4.y; As[lc+2][lr] = a4.z; As[lc+3][lr] = a4.w;
        int gn = bn + lr;
        float4 b4 = make_float4(0.f,0.f,0.f,0.f);
        if (gn < Nc) b4 = *reinterpret_cast<const float4*>(&Bw[(size_t)gn*K + k0 + lc]);
        Bs[lc+0][lr] = b4.x; Bs[lc+1][lr] = b4.y; Bs[lc+2][lr] = b4.z; Bs[lc+3][lr] = b4.w;
        __syncthreads();
#pragma unroll
        for (int k = 0; k < BK; k++) {
            float4 a0 = *reinterpret_cast<const float4*>(&As[k][ty*8]);
            float4 a1 = *reinterpret_cast<const float4*>(&As[k][ty*8+4]);
            float4 b0 = *reinterpret_cast<const float4*>(&Bs[k][tx*8]);
            float4 b1 = *reinterpret_cast<const float4*>(&Bs[k][tx*8+4]);
            float av[8] = {a0.x,a0.y,a0.z,a0.w,a1.x,a1.y,a1.z,a1.w};
            float bv[8] = {b0.x,b0.y,b0.z,b0.w,b1.x,b1.y,b1.z,b1.w};
#pragma unroll
            for (int i = 0; i < 8; i++)
#pragma unroll
                for (int j = 0; j < 8; j++) acc[i][j] += av[i]*bv[j];
        }
        __syncthreads();
    }

#pragma unroll
    for (int i = 0; i < 8; i++) {
        int row = bm + ty*8 + i;
        if (row >= M) continue;
#pragma unroll
        for (int j = 0; j < 8; j++) {
            int col = bn + tx*8 + j;
            float v = acc[i][j];
            if (EPI == 1) v += bias[col] + res[(size_t)row*Nc + col];
            if (EPI == 2) {
                v += bias[col];
                v = 0.5f * v * (1.0f + erff(v * 0.70710678118654752f));
            }
            C[(size_t)row*Nc + col] = v;
        }
    }
}

// ---------------- fused attention per (b,h): K/V resident in smem ----------------
__global__ void attn_kernel(const float* __restrict__ mask) {
    extern __shared__ float dyn[];
    float* Ks = dyn;                 // 385*65
    float* Vs = dyn + 385*65;        // 385*65
    __shared__ float q_s[64];
    __shared__ float sc[385];
    __shared__ float red[256];
    __shared__ float accs[256];

    int bh = blockIdx.x;
    int b = bh >> 3, h = bh & 7;
    int t = threadIdx.x;
    const float* qkvb = g_qkv + (size_t)b * NN * TDIM;

    for (int i = t; i < NN*HD; i += 256) {
        int m = i >> 6, d = i & 63;
        Ks[m*65 + d] = qkvb[(size_t)m*TDIM + DIM     + h*HD + d];
        Vs[m*65 + d] = qkvb[(size_t)m*TDIM + 2*DIM   + h*HD + d];
    }
    __syncthreads();

    const float scale = 0.125f;                 // hd^-0.5 = 1/8
    const float addc  = 1e-6f / (float)NN;
    int d = t & 63, q4 = t >> 6;

    for (int n = 0; n < NN; n++) {
        if (t < 64) q_s[t] = qkvb[(size_t)n*TDIM + h*HD + t];
        __syncthreads();

        float lmax = -INFINITY;
        for (int m = t; m < NN; m += 256) {
            float dot = 0.f;
#pragma unroll
            for (int dd = 0; dd < 64; dd++) dot += q_s[dd] * Ks[m*65 + dd];
            dot *= scale;
            sc[m] = dot;
            lmax = fmaxf(lmax, dot);
        }
        red[t] = lmax; __syncthreads();
        for (int s = 128; s > 0; s >>= 1) {
            if (t < s) red[t] = fmaxf(red[t], red[t+s]);
            __syncthreads();
        }
        float mx = red[0];
        __syncthreads();

        float lsum = 0.f;
        const float* mrow = mask + ((size_t)b*NN + n) * NN;
        for (int m = t; m < NN; m += 256) {
            float e = expf(sc[m] - mx) * mrow[m];
            sc[m] = e;
            lsum += e;
        }
        red[t] = lsum; __syncthreads();
        for (int s = 128; s > 0; s >>= 1) {
            if (t < s) red[t] += red[t+s];
            __syncthreads();
        }
        float inv = 1.0f / (red[0] + 1e-6f);
        __syncthreads();

        for (int m = t; m < NN; m += 256) sc[m] = (sc[m] + addc) * inv;
        __syncthreads();

        if (n == 0) {
            for (int j = t; j < 384; j += 256)
                g_clsP[((size_t)b*HH + h)*384 + j] = sc[1 + j] * 0.125f;
        }

        float partial = 0.f;
        for (int m = q4; m < NN; m += 4) partial += sc[m] * Vs[m*65 + d];
        accs[t] = partial; __syncthreads();
        if (t < 64) {
            float o = accs[d] + accs[64+d] + accs[128+d] + accs[192+d];
            g_xatt[((size_t)(b*NN + n))*DIM + h*HD + d] = o;
        }
        __syncthreads();
    }
}

// ---------------- cls head reduce ----------------
__global__ void cls_reduce_kernel() {
    int i = blockIdx.x*256 + threadIdx.x;
    if (i < BB*384) {
        int b = i / 384, j = i % 384;
        float s = 0.f;
#pragma unroll
        for (int h = 0; h < HH; h++) s += g_clsP[((size_t)b*HH + h)*384 + j];
        g_cls[i] = s;
    }
}

// ---------------- per-(b,group) exact top-k (jax tie semantics) ----------------
__global__ void topk_kernel(float* __restrict__ out) {
    const int nsz_[3]  = {64, 192, 128};
    const int kk_[3]   = {KA, KM, KS};
    const int base_[3] = {0, 64, 256};
    const int ib_[3]   = {0, KA, KA+KM};
    const long long ob_[3] = {OFF_IA, OFF_IM, OFF_IS};
    const int os_[3]   = {KA, KM, KS};

    int b = blockIdx.x / 3, g = blockIdx.x % 3;
    int nsz = nsz_[g], kk = kk_[g];
    __shared__ float v[192];
    __shared__ float rv[256];
    __shared__ int   ri[256];
    int t = threadIdx.x;
    if (t < nsz) v[t] = g_cls[b*384 + base_[g] + t];
    __syncthreads();

    for (int i = 0; i < kk; i++) {
        rv[t] = (t < nsz) ? v[t] : -INFINITY;
        ri[t] = t;
        __syncthreads();
        for (int s = 128; s > 0; s >>= 1) {
            if (t < s) {
                float v2 = rv[t+s]; int i2 = ri[t+s];
                if (v2 > rv[t] || (v2 == rv[t] && i2 < ri[t])) { rv[t] = v2; ri[t] = i2; }
            }
            __syncthreads();
        }
        if (t == 0) {
            int w = ri[0];
            g_idx[b*(KA+KM+KS) + ib_[g] + i] = w;
            out[ob_[g] + (long long)b*os_[g] + i] = (float)w;
            v[w] = -INFINITY;
        }
        __syncthreads();
    }
}

// ---------------- gather pruned rows ----------------
__global__ void gather_kernel() {
    int r = blockIdx.x;
    int b = r / RN, p = r % RN;
    int s;
    if (p == 0)            s = 0;
    else if (p < 1+KA)     s = 1   + g_idx[b*(KA+KM+KS) + (p-1)];
    else if (p < 1+KA+KM)  s = 65  + g_idx[b*(KA+KM+KS) + KA + (p-1-KA)];
    else                   s = 257 + g_idx[b*(KA+KM+KS) + KA+KM + (p-1-KA-KM)];
    const float4* src = reinterpret_cast<const float4*>(g_xres + ((size_t)(b*NN + s))*DIM);
    float4* dst = reinterpret_cast<float4*>(g_xg + (size_t)r*DIM);
    dst[threadIdx.x] = src[threadIdx.x];
}

// ---------------- new_mask is provably all-ones ----------------
__global__ void mask_fill_kernel(float* __restrict__ out) {
    long long i = (long long)blockIdx.x*256 + threadIdx.x;
    if (i < MASK_SZ) out[OFF_MASK + i] = 1.0f;
}

// ---------------- launcher ----------------
extern "C" void kernel_launch(void* const* d_in, const int* in_sizes, int n_in,
                              void* d_out, int out_size) {
    const float* x     = (const float*)d_in[0];
    const float* amask = (const float*)d_in[1];
    const float* Wqkv  = (const float*)d_in[5];
    const float* Wproj = (const float*)d_in[6];
    const float* bproj = (const float*)d_in[7];
    const float* g1    = (const float*)d_in[8];
    const float* b1    = (const float*)d_in[9];
    const float* g2    = (const float*)d_in[10];
    const float* b2    = (const float*)d_in[11];
    const float* Wfc1  = (const float*)d_in[12];
    const float* bfc1  = (const float*)d_in[13];
    const float* Wfc2  = (const float*)d_in[14];
    const float* bfc2  = (const float*)d_in[15];
    float* out = (float*)d_out;

    // resolve scratch device pointers
    float *p_xn, *p_qkv, *p_xatt, *p_xres, *p_xg, *p_xn2, *p_h;
    cudaGetSymbolAddress((void**)&p_xn,   g_xn);
    cudaGetSymbolAddress((void**)&p_qkv,  g_qkv);
    cudaGetSymbolAddress((void**)&p_xatt, g_xatt);
    cudaGetSymbolAddress((void**)&p_xres, g_xres);
    cudaGetSymbolAddress((void**)&p_xg,   g_xg);
    cudaGetSymbolAddress((void**)&p_xn2,  g_xn2);
    cudaGetSymbolAddress((void**)&p_h,    g_h);

    const int ATTN_SMEM = 2 * 385 * 65 * (int)sizeof(float);  // 200,200 B
    cudaFuncSetAttribute(attn_kernel, cudaFuncAttributeMaxDynamicSharedMemorySize, ATTN_SMEM);

    // 1) LN1
    ln_kernel<<<M1, 256>>>(x, g1, b1, p_xn);
    // 2) QKV GEMM
    gemm_tn<0><<<dim3(TDIM/128, (M1+127)/128), 256>>>(p_xn, Wqkv, nullptr, nullptr, p_qkv, M1, TDIM, DIM);
    // 3) attention (fused softmax + AV + cls row)
    attn_kernel<<<BB*HH, 256, ATTN_SMEM>>>(amask);
    // 4) proj + bias + residual
    gemm_tn<1><<<dim3(DIM/128, (M1+127)/128), 256>>>(p_xatt, Wproj, bproj, x, p_xres, M1, DIM, DIM);
    // 5) cls reduce + top-k (writes idx floats into d_out)
    cls_reduce_kernel<<<(BB*384 + 255)/256, 256>>>();
    topk_kernel<<<BB*3, 256>>>(out);
    // 6) gather pruned tokens
    gather_kernel<<<M2, 128>>>();
    // 7) new_mask = ones
    mask_fill_kernel<<<(int)((MASK_SZ + 255)/256), 256>>>(out);
    // 8) LN2
    ln_kernel<<<M2, 256>>>(p_xg, g2, b2, p_xn2);
    // 9) fc1 + bias + exact GELU
    gemm_tn<2><<<dim3(MLP/128, (M2+127)/128), 256>>>(p_xn2, Wfc1, bfc1, nullptr, p_h, M2, MLP, DIM);
    // 10) fc2 + bias + residual -> final x into d_out
    gemm_tn<1><<<dim3(DIM/128, (M2+127)/128), 256>>>(p_h, Wfc2, bfc2, p_xg, out, M2, DIM, MLP);
}

// round 4
// speedup vs baseline: 2.5753x; 2.5721x over previous
#include <cuda_runtime.h>
#include <math.h>
#include <stdint.h>

#define BB 32
#define NN 385
#define DIM 512
#define HH 8
#define HD 64
#define TDIM 1536
#define MLP 2048
#define KA 45
#define KM 135
#define KS 90
#define RN 271
#define M1 (BB*NN)
#define M2 (BB*RN)

#define X_SZ   ((long long)BB*RN*DIM)
#define OFF_IA (X_SZ)
#define OFF_IM (OFF_IA + (long long)BB*KA)
#define OFF_IS (OFF_IM + (long long)BB*KM)
#define OFF_MASK (OFF_IS + (long long)BB*KS)
#define MASK_SZ ((long long)BB*RN*RN)

__device__ float g_xn  [M1*DIM];
__device__ float g_qkv [(size_t)M1*TDIM];
__device__ float g_xatt[M1*DIM];
__device__ float g_xres[M1*DIM];
__device__ float g_clsP[BB*HH*384];
__device__ float g_cls [BB*384];
__device__ int   g_idx [BB*(KA+KM+KS)];
__device__ float g_xg  [M2*DIM];
__device__ float g_xn2 [M2*DIM];
__device__ float g_h   [(size_t)M2*MLP];

__device__ __forceinline__ float tf32_rn(float x) {
    uint32_t u; asm("cvt.rna.tf32.f32 %0, %1;" : "=r"(u) : "f"(x));
    return __uint_as_float(u);
}
__device__ __forceinline__ void mma8(float* c, const uint32_t* a, const uint32_t* b) {
    asm volatile("mma.sync.aligned.m16n8k8.row.col.f32.tf32.tf32.f32 "
        "{%0,%1,%2,%3}, {%4,%5,%6,%7}, {%8,%9}, {%0,%1,%2,%3};\n"
        : "+f"(c[0]), "+f"(c[1]), "+f"(c[2]), "+f"(c[3])
        : "r"(a[0]), "r"(a[1]), "r"(a[2]), "r"(a[3]), "r"(b[0]), "r"(b[1]));
}

// ---------------- LayerNorm ----------------
__global__ void ln_kernel(const float* __restrict__ in, const float* __restrict__ g,
                          const float* __restrict__ bta, float* __restrict__ out) {
    int r = blockIdx.x, t = threadIdx.x;
    const float* xr = in + (size_t)r * DIM;
    float a = xr[t], c = xr[t + 256];
    __shared__ float rs[256], rq[256];
    rs[t] = a + c; rq[t] = a*a + c*c;
    __syncthreads();
    for (int st = 128; st > 0; st >>= 1) {
        if (t < st) { rs[t] += rs[t+st]; rq[t] += rq[t+st]; }
        __syncthreads();
    }
    float mu  = rs[0] * (1.0f/512.0f);
    float var = rq[0] * (1.0f/512.0f) - mu*mu;
    float inv = rsqrtf(var + 1e-5f);
    out[(size_t)r*DIM + t]       = (a - mu) * inv * g[t]     + bta[t];
    out[(size_t)r*DIM + t + 256] = (c - mu) * inv * g[t+256] + bta[t+256];
}

// ---------------- fp32 SGEMM (R1-proven numerics) for QKV ----------------
__global__ void gemm_f32(const float* __restrict__ A, const float* __restrict__ Bw,
                         float* __restrict__ C, int M, int Nc, int K) {
    const int BK = 8;
    __shared__ float As[BK][128];
    __shared__ float Bs[BK][128];
    int bm = blockIdx.y * 128, bn = blockIdx.x * 128;
    int tid = threadIdx.x;
    int tx = tid & 15, ty = tid >> 4;
    int lr = tid >> 1, lc = (tid & 1) * 4;

    float acc[8][8];
#pragma unroll
    for (int i = 0; i < 8; i++)
#pragma unroll
        for (int j = 0; j < 8; j++) acc[i][j] = 0.f;

    for (int k0 = 0; k0 < K; k0 += BK) {
        int gr = bm + lr;
        float4 a4 = make_float4(0.f,0.f,0.f,0.f);
        if (gr < M) a4 = *reinterpret_cast<const float4*>(&A[(size_t)gr*K + k0 + lc]);
        As[lc+0][lr] = a4.x; As[lc+1][lr] = a4.y; As[lc+2][lr] = a4.z; As[lc+3][lr] = a4.w;
        int gn = bn + lr;
        float4 b4 = *reinterpret_cast<const float4*>(&Bw[(size_t)gn*K + k0 + lc]);
        Bs[lc+0][lr] = b4.x; Bs[lc+1][lr] = b4.y; Bs[lc+2][lr] = b4.z; Bs[lc+3][lr] = b4.w;
        __syncthreads();
#pragma unroll
        for (int k = 0; k < BK; k++) {
            float4 a0 = *reinterpret_cast<const float4*>(&As[k][ty*8]);
            float4 a1 = *reinterpret_cast<const float4*>(&As[k][ty*8+4]);
            float4 b0 = *reinterpret_cast<const float4*>(&Bs[k][tx*8]);
            float4 b1 = *reinterpret_cast<const float4*>(&Bs[k][tx*8+4]);
            float av[8] = {a0.x,a0.y,a0.z,a0.w,a1.x,a1.y,a1.z,a1.w};
            float bv[8] = {b0.x,b0.y,b0.z,b0.w,b1.x,b1.y,b1.z,b1.w};
#pragma unroll
            for (int i = 0; i < 8; i++)
#pragma unroll
                for (int j = 0; j < 8; j++) acc[i][j] += av[i]*bv[j];
        }
        __syncthreads();
    }
#pragma unroll
    for (int i = 0; i < 8; i++) {
        int row = bm + ty*8 + i;
        if (row >= M) continue;
#pragma unroll
        for (int j = 0; j < 8; j++)
            C[(size_t)row*Nc + bn + tx*8 + j] = acc[i][j];
    }
}

// ---------------- TF32 MMA GEMM (tolerance-level outputs only) ----------------
#define GTS (128*20)
template<int EPI>
__device__ __forceinline__ float epi_f(float v, const float* bias, const float* res,
                                       size_t row, int col, int Nc) {
    if (EPI == 1) v += bias[col] + res[row*(size_t)Nc + col];
    if (EPI == 2) { v += bias[col]; v = 0.5f*v*(1.0f + erff(v*0.70710678118654752f)); }
    return v;
}
__device__ __forceinline__ void cvt_store4(float* hi, int idx, float4 v) {
    *(float4*)&hi[idx] = make_float4(tf32_rn(v.x), tf32_rn(v.y), tf32_rn(v.z), tf32_rn(v.w));
}

template<int EPI>
__global__ void __launch_bounds__(256) gemm_mma(
    const float* __restrict__ A, const float* __restrict__ Bw,
    const float* __restrict__ bias, const float* __restrict__ res,
    float* __restrict__ C, int M, int Nc, int K)
{
    extern __shared__ float sm[];
    float* Ah = sm;
    float* Bh = sm + 2*GTS;

    int tid = threadIdx.x;
    int bm = blockIdx.y*128, bn = blockIdx.x*128;
    int lane = tid & 31, g = lane >> 2, tg = lane & 3;
    int warp = tid >> 5;
    int wm = (warp & 1) * 64, wn = (warp >> 1) * 32;

    int r0 = tid >> 2;
    int c0 = (tid & 3) * 4;
    bool v0 = (bm + r0) < M;
    bool v1 = (bm + r0 + 64) < M;
    const float* Ag0 = A  + (size_t)(bm + r0)      * K + c0;
    const float* Ag1 = A  + (size_t)(bm + r0 + 64) * K + c0;
    const float* Bg0 = Bw + (size_t)(bn + r0)      * K + c0;
    const float* Bg1 = Bw + (size_t)(bn + r0 + 64) * K + c0;

    float acc[4][4][4];
#pragma unroll
    for (int i = 0; i < 4; i++)
#pragma unroll
        for (int j = 0; j < 4; j++)
#pragma unroll
            for (int e = 0; e < 4; e++) acc[i][j][e] = 0.f;

    const float4 z4 = make_float4(0.f,0.f,0.f,0.f);
    cvt_store4(Ah, r0*20 + c0,      v0 ? *(const float4*)Ag0 : z4);
    cvt_store4(Ah, (r0+64)*20 + c0, v1 ? *(const float4*)Ag1 : z4);
    cvt_store4(Bh, r0*20 + c0,      *(const float4*)Bg0);
    cvt_store4(Bh, (r0+64)*20 + c0, *(const float4*)Bg1);
    __syncthreads();

    int KT = K >> 4;
    for (int kt = 0; kt < KT; kt++) {
        int buf = kt & 1;
        bool more = (kt + 1) < KT;
        float4 na0, na1, nb0, nb1;
        if (more) {
            int ko = (kt + 1) * 16;
            na0 = v0 ? *(const float4*)(Ag0 + ko) : z4;
            na1 = v1 ? *(const float4*)(Ag1 + ko) : z4;
            nb0 = *(const float4*)(Bg0 + ko);
            nb1 = *(const float4*)(Bg1 + ko);
        }
        const float* As = Ah + buf*GTS;
        const float* Bs = Bh + buf*GTS;
#pragma unroll
        for (int ks = 0; ks < 2; ks++) {
            int kb = ks*8 + tg;
            uint32_t af[4][4], bf[4][2];
#pragma unroll
            for (int i = 0; i < 4; i++) {
                int r = wm + i*16 + g;
                af[i][0] = __float_as_uint(As[r*20 + kb]);
                af[i][1] = __float_as_uint(As[(r+8)*20 + kb]);
                af[i][2] = __float_as_uint(As[r*20 + kb + 4]);
                af[i][3] = __float_as_uint(As[(r+8)*20 + kb + 4]);
            }
#pragma unroll
            for (int j = 0; j < 4; j++) {
                int n = wn + j*8 + g;
                bf[j][0] = __float_as_uint(Bs[n*20 + kb]);
                bf[j][1] = __float_as_uint(Bs[n*20 + kb + 4]);
            }
#pragma unroll
            for (int i = 0; i < 4; i++)
#pragma unroll
                for (int j = 0; j < 4; j++) mma8(acc[i][j], af[i], bf[j]);
        }
        if (more) {
            int nb2 = (buf ^ 1) * GTS;
            cvt_store4(Ah, nb2 + r0*20 + c0,      na0);
            cvt_store4(Ah, nb2 + (r0+64)*20 + c0, na1);
            cvt_store4(Bh, nb2 + r0*20 + c0,      nb0);
            cvt_store4(Bh, nb2 + (r0+64)*20 + c0, nb1);
            __syncthreads();
        }
    }

#pragma unroll
    for (int i = 0; i < 4; i++) {
        int rr0 = bm + wm + i*16 + g;
        int rr1 = rr0 + 8;
#pragma unroll
        for (int j = 0; j < 4; j++) {
            int c = bn + wn + j*8 + tg*2;
            if (rr0 < M) {
                C[(size_t)rr0*Nc + c  ] = epi_f<EPI>(acc[i][j][0], bias, res, rr0, c,   Nc);
                C[(size_t)rr0*Nc + c+1] = epi_f<EPI>(acc[i][j][1], bias, res, rr0, c+1, Nc);
            }
            if (rr1 < M) {
                C[(size_t)rr1*Nc + c  ] = epi_f<EPI>(acc[i][j][2], bias, res, rr1, c,   Nc);
                C[(size_t)rr1*Nc + c+1] = epi_f<EPI>(acc[i][j][3], bias, res, rr1, c+1, Nc);
            }
        }
    }
}

// ---------------- fused attention: 4 queries/iter ----------------
__global__ void __launch_bounds__(256) attn_kernel(const float* __restrict__ mask) {
    extern __shared__ float dyn[];
    float* Ks   = dyn;
    float* Vs   = Ks + NN*68;
    float* sc   = Vs + NN*68;
    float* q4   = sc + 4*388;
    float* wred = q4 + 256;
    float* bmax = wred + 32;
    float* binv = bmax + 4;
    float* part = binv + 4;

    int bh = blockIdx.x, b = bh >> 3, h = bh & 7;
    int t = threadIdx.x, lane = t & 31, w = t >> 5;
    const float* qkvb = g_qkv + (size_t)b * NN * TDIM;

    for (int i = t; i < NN*16; i += 256) {
        int m = i >> 4, d4 = (i & 15) * 4;
        *(float4*)&Ks[m*68 + d4] = *(const float4*)&qkvb[(size_t)m*TDIM + DIM   + h*HD + d4];
        *(float4*)&Vs[m*68 + d4] = *(const float4*)&qkvb[(size_t)m*TDIM + 2*DIM + h*HD + d4];
    }
    __syncthreads();

    const float addc = 1e-6f / 385.0f;
    const float* mb = mask + (size_t)b * NN * NN;

    for (int n0 = 0; n0 < NN; n0 += 4) {
        {
            int q = t >> 6, d = t & 63;
            int nq = n0 + q; if (nq > NN-1) nq = NN-1;
            q4[q*64 + d] = qkvb[(size_t)nq*TDIM + h*HD + d];
        }
        __syncthreads();

        float lm0=-1e30f, lm1=-1e30f, lm2=-1e30f, lm3=-1e30f;
        for (int m = t; m < NN; m += 256) {
            float s0=0.f, s1=0.f, s2=0.f, s3=0.f;
#pragma unroll
            for (int d4 = 0; d4 < 64; d4 += 4) {
                float4 k  = *(float4*)&Ks[m*68 + d4];
                float4 qa = *(float4*)&q4[d4];
                float4 qb = *(float4*)&q4[64 + d4];
                float4 qc = *(float4*)&q4[128 + d4];
                float4 qd = *(float4*)&q4[192 + d4];
                s0 += k.x*qa.x + k.y*qa.y + k.z*qa.z + k.w*qa.w;
                s1 += k.x*qb.x + k.y*qb.y + k.z*qb.z + k.w*qb.w;
                s2 += k.x*qc.x + k.y*qc.y + k.z*qc.z + k.w*qc.w;
                s3 += k.x*qd.x + k.y*qd.y + k.z*qd.z + k.w*qd.w;
            }
            s0 *= 0.125f; s1 *= 0.125f; s2 *= 0.125f; s3 *= 0.125f;
            sc[m] = s0; sc[388+m] = s1; sc[776+m] = s2; sc[1164+m] = s3;
            lm0 = fmaxf(lm0, s0); lm1 = fmaxf(lm1, s1);
            lm2 = fmaxf(lm2, s2); lm3 = fmaxf(lm3, s3);
        }
#pragma unroll
        for (int off = 16; off; off >>= 1) {
            lm0 = fmaxf(lm0, __shfl_xor_sync(0xFFFFFFFFu, lm0, off));
            lm1 = fmaxf(lm1, __shfl_xor_sync(0xFFFFFFFFu, lm1, off));
            lm2 = fmaxf(lm2, __shfl_xor_sync(0xFFFFFFFFu, lm2, off));
            lm3 = fmaxf(lm3, __shfl_xor_sync(0xFFFFFFFFu, lm3, off));
        }
        if (lane == 0) { wred[w*4+0]=lm0; wred[w*4+1]=lm1; wred[w*4+2]=lm2; wred[w*4+3]=lm3; }
        __syncthreads();
        if (t < 4) {
            float v = wred[t];
#pragma unroll
            for (int wi = 1; wi < 8; wi++) v = fmaxf(v, wred[wi*4 + t]);
            bmax[t] = v;
        }
        __syncthreads();

        float ls0=0.f, ls1=0.f, ls2=0.f, ls3=0.f;
        float bm0=bmax[0], bm1=bmax[1], bm2=bmax[2], bm3=bmax[3];
        int nq1 = (n0+1 < NN) ? n0+1 : NN-1;
        int nq2 = (n0+2 < NN) ? n0+2 : NN-1;
        int nq3 = (n0+3 < NN) ? n0+3 : NN-1;
        const float* mr0 = mb + (size_t)n0  * NN;
        const float* mr1 = mb + (size_t)nq1 * NN;
        const float* mr2 = mb + (size_t)nq2 * NN;
        const float* mr3 = mb + (size_t)nq3 * NN;
        for (int m = t; m < NN; m += 256) {
            float e0 = expf(sc[m]      - bm0) * mr0[m];
            float e1 = expf(sc[388+m]  - bm1) * mr1[m];
            float e2 = expf(sc[776+m]  - bm2) * mr2[m];
            float e3 = expf(sc[1164+m] - bm3) * mr3[m];
            sc[m] = e0; sc[388+m] = e1; sc[776+m] = e2; sc[1164+m] = e3;
            ls0 += e0; ls1 += e1; ls2 += e2; ls3 += e3;
        }
#pragma unroll
        for (int off = 16; off; off >>= 1) {
            ls0 += __shfl_xor_sync(0xFFFFFFFFu, ls0, off);
            ls1 += __shfl_xor_sync(0xFFFFFFFFu, ls1, off);
            ls2 += __shfl_xor_sync(0xFFFFFFFFu, ls2, off);
            ls3 += __shfl_xor_sync(0xFFFFFFFFu, ls3, off);
        }
        if (lane == 0) { wred[w*4+0]=ls0; wred[w*4+1]=ls1; wred[w*4+2]=ls2; wred[w*4+3]=ls3; }
        __syncthreads();
        if (t < 4) {
            float s = 0.f;
#pragma unroll
            for (int wi = 0; wi < 8; wi++) s += wred[wi*4 + t];
            binv[t] = 1.0f / (s + 1e-6f);
        }
        __syncthreads();

        if (n0 == 0) {
            float iv = binv[0];
            for (int j = t; j < 384; j += 256)
                g_clsP[((size_t)b*HH + h)*384 + j] = (sc[1+j] + addc) * iv * 0.125f;
        }

        {
            int dd = lane * 2;
            float iv0=binv[0], iv1=binv[1], iv2=binv[2], iv3=binv[3];
            float ax0=0,ay0=0, ax1=0,ay1=0, ax2=0,ay2=0, ax3=0,ay3=0;
            for (int m = w; m < NN; m += 8) {
                float2 v = *(float2*)&Vs[m*68 + dd];
                float p0 = (sc[m]      + addc) * iv0;
                float p1 = (sc[388+m]  + addc) * iv1;
                float p2 = (sc[776+m]  + addc) * iv2;
                float p3 = (sc[1164+m] + addc) * iv3;
                ax0 += p0*v.x; ay0 += p0*v.y;
                ax1 += p1*v.x; ay1 += p1*v.y;
                ax2 += p2*v.x; ay2 += p2*v.y;
                ax3 += p3*v.x; ay3 += p3*v.y;
            }
            int base = (w*4)*64 + dd;
            part[base      ] = ax0; part[base + 1  ] = ay0;
            part[base + 64 ] = ax1; part[base + 65 ] = ay1;
            part[base + 128] = ax2; part[base + 129] = ay2;
            part[base + 192] = ax3; part[base + 193] = ay3;
        }
        __syncthreads();
        {
            int q = t >> 6, d = t & 63;
            int n = n0 + q;
            if (n < NN) {
                float s = 0.f;
#pragma unroll
                for (int sp = 0; sp < 8; sp++) s += part[(sp*4 + q)*64 + d];
                g_xatt[((size_t)(b*NN + n))*DIM + h*HD + d] = s;
            }
        }
        __syncthreads();
    }
}

// ---------------- cls reduce ----------------
__global__ void cls_reduce_kernel() {
    int i = blockIdx.x*256 + threadIdx.x;
    if (i < BB*384) {
        int b = i / 384, j = i % 384;
        float s = 0.f;
#pragma unroll
        for (int h = 0; h < HH; h++) s += g_clsP[((size_t)b*HH + h)*384 + j];
        g_cls[i] = s;
    }
}

// ---------------- top-k (exact jax tie semantics) ----------------
__global__ void topk_kernel(float* __restrict__ out) {
    const int nsz_[3]  = {64, 192, 128};
    const int kk_[3]   = {KA, KM, KS};
    const int base_[3] = {0, 64, 256};
    const int ib_[3]   = {0, KA, KA+KM};
    const long long ob_[3] = {OFF_IA, OFF_IM, OFF_IS};
    const int os_[3]   = {KA, KM, KS};

    int b = blockIdx.x / 3, g = blockIdx.x % 3;
    int nsz = nsz_[g], kk = kk_[g];
    __shared__ float v[192];
    __shared__ float rv[256];
    __shared__ int   ri[256];
    int t = threadIdx.x;
    if (t < nsz) v[t] = g_cls[b*384 + base_[g] + t];
    __syncthreads();

    for (int i = 0; i < kk; i++) {
        rv[t] = (t < nsz) ? v[t] : -INFINITY;
        ri[t] = t;
        __syncthreads();
        for (int s = 128; s > 0; s >>= 1) {
            if (t < s) {
                float v2 = rv[t+s]; int i2 = ri[t+s];
                if (v2 > rv[t] || (v2 == rv[t] && i2 < ri[t])) { rv[t] = v2; ri[t] = i2; }
            }
            __syncthreads();
        }
        if (t == 0) {
            int wn = ri[0];
            g_idx[b*(KA+KM+KS) + ib_[g] + i] = wn;
            out[ob_[g] + (long long)b*os_[g] + i] = (float)wn;
            v[wn] = -INFINITY;
        }
        __syncthreads();
    }
}

// ---------------- gather ----------------
__global__ void gather_kernel() {
    int r = blockIdx.x;
    int b = r / RN, p = r % RN;
    int s;
    if (p == 0)            s = 0;
    else if (p < 1+KA)     s = 1   + g_idx[b*(KA+KM+KS) + (p-1)];
    else if (p < 1+KA+KM)  s = 65  + g_idx[b*(KA+KM+KS) + KA + (p-1-KA)];
    else                   s = 257 + g_idx[b*(KA+KM+KS) + KA+KM + (p-1-KA-KM)];
    const float4* src = reinterpret_cast<const float4*>(g_xres + ((size_t)(b*NN + s))*DIM);
    float4* dst = reinterpret_cast<float4*>(g_xg + (size_t)r*DIM);
    dst[threadIdx.x] = src[threadIdx.x];
}

// ---------------- mask = ones ----------------
__global__ void mask_fill_kernel(float* __restrict__ out) {
    long long i = (long long)blockIdx.x*256 + threadIdx.x;
    if (i < MASK_SZ) out[OFF_MASK + i] = 1.0f;
}

// ---------------- launcher ----------------
extern "C" void kernel_launch(void* const* d_in, const int* in_sizes, int n_in,
                              void* d_out, int out_size) {
    const float* x     = (const float*)d_in[0];
    const float* amask = (const float*)d_in[1];
    const float* Wqkv  = (const float*)d_in[5];
    const float* Wproj = (const float*)d_in[6];
    const float* bproj = (const float*)d_in[7];
    const float* g1    = (const float*)d_in[8];
    const float* b1    = (const float*)d_in[9];
    const float* g2    = (const float*)d_in[10];
    const float* b2    = (const float*)d_in[11];
    const float* Wfc1  = (const float*)d_in[12];
    const float* bfc1  = (const float*)d_in[13];
    const float* Wfc2  = (const float*)d_in[14];
    const float* bfc2  = (const float*)d_in[15];
    float* out = (float*)d_out;

    float *p_xn, *p_qkv, *p_xatt, *p_xres, *p_xg, *p_xn2, *p_h;
    cudaGetSymbolAddress((void**)&p_xn,   g_xn);
    cudaGetSymbolAddress((void**)&p_qkv,  g_qkv);
    cudaGetSymbolAddress((void**)&p_xatt, g_xatt);
    cudaGetSymbolAddress((void**)&p_xres, g_xres);
    cudaGetSymbolAddress((void**)&p_xg,   g_xg);
    cudaGetSymbolAddress((void**)&p_xn2,  g_xn2);
    cudaGetSymbolAddress((void**)&p_h,    g_h);

    const int SMEM_S = 4*GTS*4;   // 40960 B
    const int ATTN_SMEM = (2*NN*68 + 4*388 + 256 + 32 + 8 + 2048) * 4;
    cudaFuncSetAttribute(gemm_mma<1>, cudaFuncAttributeMaxDynamicSharedMemorySize, SMEM_S);
    cudaFuncSetAttribute(gemm_mma<2>, cudaFuncAttributeMaxDynamicSharedMemorySize, SMEM_S);
    cudaFuncSetAttribute(attn_kernel, cudaFuncAttributeMaxDynamicSharedMemorySize, ATTN_SMEM);

    ln_kernel<<<M1, 256>>>(x, g1, b1, p_xn);
    // QKV in fp32 (feeds exact top-k; R1-proven numerics)
    gemm_f32<<<dim3(TDIM/128, (M1+127)/128), 256>>>(p_xn, Wqkv, p_qkv, M1, TDIM, DIM);
    attn_kernel<<<BB*HH, 256, ATTN_SMEM>>>(amask);
    gemm_mma<1><<<dim3(DIM/128, (M1+127)/128), 256, SMEM_S>>>(p_xatt, Wproj, bproj, x, p_xres, M1, DIM, DIM);
    cls_reduce_kernel<<<(BB*384 + 255)/256, 256>>>();
    topk_kernel<<<BB*3, 256>>>(out);
    gather_kernel<<<M2, 128>>>();
    mask_fill_kernel<<<(int)((MASK_SZ + 255)/256), 256>>>(out);
    ln_kernel<<<M2, 256>>>(p_xg, g2, b2, p_xn2);
    gemm_mma<2><<<dim3(MLP/128, (M2+127)/128), 256, SMEM_S>>>(p_xn2, Wfc1, bfc1, nullptr, p_h, M2, MLP, DIM);
    gemm_mma<1><<<dim3(DIM/128, (M2+127)/128), 256, SMEM_S>>>(p_h, Wfc2, bfc2, p_xg, out, M2, DIM, MLP);
}